// round 17
// baseline (speedup 1.0000x reference)
#include <cuda_runtime.h>
#include <cuda_bf16.h>
#include <cstdint>

// Problem constants: B=64, D=2048, UNITS=1024, NW=64
#define Dd     2048
#define UNITSn 1024
#define NWn    64

// bf16 hi/lo planes: W [u][k] (4MB each), X [b][k] (256KB each).
__device__ __align__(16) __nv_bfloat16 g_Whi[UNITSn * Dd];
__device__ __align__(16) __nv_bfloat16 g_Wlo[UNITSn * Dd];
__device__ __align__(16) __nv_bfloat16 g_Xhi[64 * Dd];
__device__ __align__(16) __nv_bfloat16 g_Xlo[64 * Dd];

__device__ __forceinline__ unsigned mdiv(unsigned e, unsigned magic) {
    return (unsigned)(((unsigned long long)e * magic) >> 32);
}
__device__ __forceinline__ unsigned pack_bf16x2(float f0, float f1) {
    unsigned short a = __bfloat16_as_ushort(__float2bfloat16_rn(f0));
    unsigned short b = __bfloat16_as_ushort(__float2bfloat16_rn(f1));
    return (unsigned)a | ((unsigned)b << 16);
}
__device__ __forceinline__ float bf16_hi_f(float f) {
    return __bfloat162float(__float2bfloat16_rn(f));
}
__device__ __forceinline__ unsigned smem_u32(const void* p) {
    unsigned a;
    asm("{ .reg .u64 t; cvta.to.shared.u64 t, %1; cvt.u32.u64 %0, t; }"
        : "=r"(a) : "l"(p));
    return a;
}
__device__ __forceinline__ void cp16(unsigned s, const void* g) {
    asm volatile("cp.async.cg.shared.global [%0], [%1], 16;" :: "r"(s), "l"(g));
}
__device__ __forceinline__ void cp_commit() { asm volatile("cp.async.commit_group;"); }
__device__ __forceinline__ void cp_wait_all() {
    asm volatile("cp.async.wait_group 0;" ::: "memory");
}

// HMMA m16n8k16 bf16 -> fp32 accumulate.
__device__ __forceinline__ void mma_bf16(float* d, unsigned a0, unsigned a1,
                                         unsigned a2, unsigned a3,
                                         unsigned b0, unsigned b1) {
    asm volatile(
        "mma.sync.aligned.m16n8k16.row.col.f32.bf16.bf16.f32 "
        "{%0,%1,%2,%3}, {%4,%5,%6,%7}, {%8,%9}, {%0,%1,%2,%3};"
        : "+f"(d[0]), "+f"(d[1]), "+f"(d[2]), "+f"(d[3])
        : "r"(a0), "r"(a1), "r"(a2), "r"(a3), "r"(b0), "r"(b1));
}
// ldmatrix x4 (sm_75+): 4 8x8 b16 matrices, per-lane row addresses.
__device__ __forceinline__ void ldsm_x4(unsigned& r0, unsigned& r1,
                                        unsigned& r2, unsigned& r3, unsigned a) {
    asm volatile("ldmatrix.sync.aligned.m8n8.x4.shared.b16 {%0,%1,%2,%3}, [%4];"
                 : "=r"(r0), "=r"(r1), "=r"(r2), "=r"(r3) : "r"(a));
}

// ---------------------------------------------------------------------------
// Kernel 1: build W bf16 hi/lo planes (2 units per CTA, 512 CTAs x 256 thr),
// convert x to bf16 hi/lo planes ONCE, seed out = bias. (Unchanged from R16.)
// ---------------------------------------------------------------------------
#define BTHR 256
#define KSTR 2080
__global__ __launch_bounds__(BTHR) void build_w_kernel(const int* __restrict__ indices,
                                                       const float* __restrict__ w,
                                                       const float* __restrict__ x,
                                                       const float* __restrict__ bias,
                                                       float* __restrict__ out,
                                                       int L, unsigned magicL) {
    __shared__ unsigned st[2 * KSTR];
    __shared__ unsigned wpk[NWn];
    const int tid = threadIdx.x;
    const int u0  = blockIdx.x * 2;

    if (tid < 128) {
        const int o = blockIdx.x * 128 + tid;
        out[o] = bias[o & (UNITSn - 1)];
    }
    if (tid >= 128 && tid < 192) {
        const int o = (blockIdx.x * 64 + (tid - 128)) * 4;
        float4 f = __ldg((const float4*)(x + o));
        float h0 = bf16_hi_f(f.x), h1 = bf16_hi_f(f.y);
        float h2 = bf16_hi_f(f.z), h3 = bf16_hi_f(f.w);
        uint2 hv, lv;
        hv.x = pack_bf16x2(h0, h1); hv.y = pack_bf16x2(h2, h3);
        lv.x = pack_bf16x2(f.x - h0, f.y - h1);
        lv.y = pack_bf16x2(f.z - h2, f.w - h3);
        *(uint2*)&g_Xhi[o] = hv;
        *(uint2*)&g_Xlo[o] = lv;
    }
    if (tid < NWn) {
        const float wv = w[tid];
        const float h  = bf16_hi_f(wv);
        wpk[tid] = (unsigned)__bfloat16_as_ushort(__float2bfloat16_rn(h)) |
                   ((unsigned)__bfloat16_as_ushort(__float2bfloat16_rn(wv - h)) << 16);
    }
    #pragma unroll
    for (int i = 0; i < (2 * KSTR + 4 * BTHR - 1) / (4 * BTHR); i++) {
        const int idx = (i * BTHR + tid) * 4;
        if (idx + 3 < 2 * KSTR)
            *(uint4*)(st + idx) = make_uint4(0u, 0u, 0u, 0u);
    }
    for (int idx = (2 * KSTR / (4 * BTHR)) * 4 * BTHR + tid; idx < 2 * KSTR; idx += BTHR)
        st[idx] = 0u;
    __syncthreads();

    {
        const int NWL4 = 16 * L;
        const int4* ind4 = (const int4*)indices + (long)u0 * NWL4;
        int e4 = tid;
        for (; e4 + BTHR < NWL4; e4 += 2 * BTHR) {
            int4 v[2], v2[2];
            #pragma unroll
            for (int uu = 0; uu < 2; uu++) {
                v[uu]  = __ldg(ind4 + (long)uu * NWL4 + e4);
                v2[uu] = __ldg(ind4 + (long)uu * NWL4 + e4 + BTHR);
            }
            #pragma unroll
            for (int h = 0; h < 2; h++) {
                const int4* vv = h ? v2 : v;
                const int e = (e4 + h * BTHR) * 4;
                const unsigned k0 = mdiv(e, magicL),     k1 = mdiv(e + 1, magicL);
                const unsigned k2 = mdiv(e + 2, magicL), k3 = mdiv(e + 3, magicL);
                #pragma unroll
                for (int uu = 0; uu < 2; uu++) {
                    unsigned* row = st + uu * KSTR;
                    unsigned p;
                    p = (unsigned)(vv[uu].x - 1); if (p < (unsigned)Dd) row[p] = wpk[k0];
                    p = (unsigned)(vv[uu].y - 1); if (p < (unsigned)Dd) row[p] = wpk[k1];
                    p = (unsigned)(vv[uu].z - 1); if (p < (unsigned)Dd) row[p] = wpk[k2];
                    p = (unsigned)(vv[uu].w - 1); if (p < (unsigned)Dd) row[p] = wpk[k3];
                }
            }
        }
        for (; e4 < NWL4; e4 += BTHR) {
            int4 v[2];
            #pragma unroll
            for (int uu = 0; uu < 2; uu++)
                v[uu] = __ldg(ind4 + (long)uu * NWL4 + e4);
            const int e = e4 * 4;
            const unsigned k0 = mdiv(e, magicL),     k1 = mdiv(e + 1, magicL);
            const unsigned k2 = mdiv(e + 2, magicL), k3 = mdiv(e + 3, magicL);
            #pragma unroll
            for (int uu = 0; uu < 2; uu++) {
                unsigned* row = st + uu * KSTR;
                unsigned p;
                p = (unsigned)(v[uu].x - 1); if (p < (unsigned)Dd) row[p] = wpk[k0];
                p = (unsigned)(v[uu].y - 1); if (p < (unsigned)Dd) row[p] = wpk[k1];
                p = (unsigned)(v[uu].z - 1); if (p < (unsigned)Dd) row[p] = wpk[k2];
                p = (unsigned)(v[uu].w - 1); if (p < (unsigned)Dd) row[p] = wpk[k3];
            }
        }
    }
    __syncthreads();

    #pragma unroll
    for (int uu = 0; uu < 2; uu++) {
        #pragma unroll
        for (int i = 0; i < 2; i++) {
            const int idx = i * BTHR + tid;
            uint4 pk = *(const uint4*)(st + uu * KSTR + idx * 4);
            uint2 hv, lv;
            hv.x = __byte_perm(pk.x, pk.y, 0x5410);
            hv.y = __byte_perm(pk.z, pk.w, 0x5410);
            lv.x = __byte_perm(pk.x, pk.y, 0x7632);
            lv.y = __byte_perm(pk.z, pk.w, 0x7632);
            const long gi = (long)(u0 + uu) * Dd + idx * 4;
            *(uint2*)&g_Whi[gi] = hv;
            *(uint2*)&g_Wlo[gi] = lv;
        }
    }
}

// ---------------------------------------------------------------------------
// Kernel 2: HMMA GEMM. Grid (16 ug, 8 ks), NOW 512 threads (16 warps = 4 per
// SMSP). Warp-group wg = warp>>3 handles k-steps wg*8..wg*8+7 (the atomic
// epilogue sums the split for free). Fragment loads via ldmatrix.x4 — 6 LDSM
// per warp per step instead of 24 scalar LDS (4x fewer instructions, much
// shorter latency chains). Padded rows (132 words) keep LDSM conflict-free.
// ---------------------------------------------------------------------------
#define ROWW  132
#define WS_HI 0
#define WS_LO (64 * ROWW)
#define XS_HI (128 * ROWW)
#define XS_LO (192 * ROWW)
#define SM_WORDS (256 * ROWW)          // 135168 B
#define GNT   512

__global__ __launch_bounds__(GNT, 1) void gemm_kernel(float* __restrict__ out) {
    extern __shared__ unsigned smw[];
    const unsigned sbase = smem_u32(smw);
    const int tid  = threadIdx.x;
    const int lane = tid & 31;
    const int warp = tid >> 5;
    const int u0   = blockIdx.x * 64;
    const int k0   = blockIdx.y * 256;

    // Prologue: 16 cp.async per thread (W hi/lo 64KB + X hi/lo 64KB).
    #pragma unroll
    for (int i = 0; i < 4; i++) {
        const int idx = i * GNT + tid;       // 0..2047 16B-chunks
        const int r   = idx >> 5;
        const int c   = idx & 31;
        const unsigned soff = (r * ROWW + c * 4) * 4;
        const long wsrc = (long)(u0 + r) * Dd + k0 + c * 8;
        const long xsrc = (long)r * Dd + k0 + c * 8;
        cp16(sbase + WS_HI * 4 + soff, &g_Whi[wsrc]);
        cp16(sbase + WS_LO * 4 + soff, &g_Wlo[wsrc]);
        cp16(sbase + XS_HI * 4 + soff, &g_Xhi[xsrc]);
        cp16(sbase + XS_LO * 4 + soff, &g_Xlo[xsrc]);
    }
    cp_commit();
    cp_wait_all();
    __syncthreads();

    const int wg  = warp >> 3;            // k-step group: steps wg*8..wg*8+7
    const int w8  = warp & 7;
    const int m0  = (w8 & 3) * 16;        // batch tile
    const int n0  = (w8 >> 2) * 32;       // unit tile
    const int s0  = wg * 8;

    // ldmatrix per-lane addresses (u32 word offsets, then *4 for bytes).
    // A (x): mat0=rows m0..7 k-lo, mat1=rows m0+8..15 k-lo, mat2/3 = k-hi.
    const int rowA   = m0 + (lane & 15);
    const int khalfA = lane >> 4;                       // 0 = k 0-7, 1 = k 8-15
    const unsigned aHi = sbase + (XS_HI + rowA * ROWW + khalfA * 4 + s0 * 8) * 4;
    const unsigned aLo = aHi + (XS_LO - XS_HI) * 4;
    // B (W): mat0=rows n..n+7 k-lo, mat1=same rows k-hi, mat2/3 = rows +8.
    const int rowB   = n0 + ((lane >> 4) << 3) + (lane & 7);
    const int khalfB = (lane >> 3) & 1;
    const unsigned b0Hi = sbase + (WS_HI + rowB * ROWW + khalfB * 4 + s0 * 8) * 4;
    const unsigned b1Hi = b0Hi + 16 * ROWW * 4;         // unit rows +16 (j=2,3)
    const unsigned b0Lo = b0Hi + (WS_LO - WS_HI) * 4;
    const unsigned b1Lo = b1Hi + (WS_LO - WS_HI) * 4;

    float dhh[4][4], dlh[4][4], dhl[4][4];
    #pragma unroll
    for (int j = 0; j < 4; j++)
        #pragma unroll
        for (int i = 0; i < 4; i++) { dhh[j][i] = 0.f; dlh[j][i] = 0.f; dhl[j][i] = 0.f; }

    #pragma unroll
    for (int s = 0; s < 8; s++) {
        const unsigned co = s * 32;       // byte offset per k-step (8 u32)
        unsigned xh[4], xl[4], bh01[4], bh23[4], bl01[4], bl23[4];
        ldsm_x4(xh[0], xh[1], xh[2], xh[3], aHi + co);
        ldsm_x4(xl[0], xl[1], xl[2], xl[3], aLo + co);
        ldsm_x4(bh01[0], bh01[1], bh01[2], bh01[3], b0Hi + co);
        ldsm_x4(bh23[0], bh23[1], bh23[2], bh23[3], b1Hi + co);
        ldsm_x4(bl01[0], bl01[1], bl01[2], bl01[3], b0Lo + co);
        ldsm_x4(bl23[0], bl23[1], bl23[2], bl23[3], b1Lo + co);

        mma_bf16(dhh[0], xh[0], xh[1], xh[2], xh[3], bh01[0], bh01[1]);
        mma_bf16(dhh[1], xh[0], xh[1], xh[2], xh[3], bh01[2], bh01[3]);
        mma_bf16(dhh[2], xh[0], xh[1], xh[2], xh[3], bh23[0], bh23[1]);
        mma_bf16(dhh[3], xh[0], xh[1], xh[2], xh[3], bh23[2], bh23[3]);
        mma_bf16(dlh[0], xl[0], xl[1], xl[2], xl[3], bh01[0], bh01[1]);
        mma_bf16(dlh[1], xl[0], xl[1], xl[2], xl[3], bh01[2], bh01[3]);
        mma_bf16(dlh[2], xl[0], xl[1], xl[2], xl[3], bh23[0], bh23[1]);
        mma_bf16(dlh[3], xl[0], xl[1], xl[2], xl[3], bh23[2], bh23[3]);
        mma_bf16(dhl[0], xh[0], xh[1], xh[2], xh[3], bl01[0], bl01[1]);
        mma_bf16(dhl[1], xh[0], xh[1], xh[2], xh[3], bl01[2], bl01[3]);
        mma_bf16(dhl[2], xh[0], xh[1], xh[2], xh[3], bl23[0], bl23[1]);
        mma_bf16(dhl[3], xh[0], xh[1], xh[2], xh[3], bl23[2], bl23[3]);
    }

    // Epilogue: merge passes; atomic k-split reduction into bias-seeded out.
    const int g   = lane >> 2;
    const int tig = lane & 3;
    #pragma unroll
    for (int j = 0; j < 4; j++) {
        const int u = u0 + n0 + j * 8 + 2 * tig;
        float* p0 = out + (long)(m0 + g) * UNITSn + u;
        float* p1 = out + (long)(m0 + g + 8) * UNITSn + u;
        atomicAdd(p0,     dhh[j][0] + dlh[j][0] + dhl[j][0]);
        atomicAdd(p0 + 1, dhh[j][1] + dlh[j][1] + dhl[j][1]);
        atomicAdd(p1,     dhh[j][2] + dlh[j][2] + dhl[j][2]);
        atomicAdd(p1 + 1, dhh[j][3] + dlh[j][3] + dhl[j][3]);
    }
}

// ---------------------------------------------------------------------------
extern "C" void kernel_launch(void* const* d_in, const int* in_sizes, int n_in,
                              void* d_out, int out_size) {
    const float* x       = (const float*)d_in[0];
    const float* w       = (const float*)d_in[1];
    const float* bias    = (const float*)d_in[2];
    const int*   indices = (const int*)d_in[3];
    float*       out     = (float*)d_out;

    const int L = in_sizes[3] / (UNITSn * NWn);
    const unsigned magicL =
        (unsigned)((0x100000000ULL + (unsigned long long)L - 1) / (unsigned long long)L);

    const int gemm_smem = SM_WORDS * (int)sizeof(unsigned);   // 135,168 B
    cudaFuncSetAttribute(gemm_kernel, cudaFuncAttributeMaxDynamicSharedMemorySize,
                         gemm_smem);

    build_w_kernel<<<512, BTHR>>>(indices, w, x, bias, out, L, magicL);
    gemm_kernel<<<dim3(16, 8), GNT, gemm_smem>>>(out);
}